// round 4
// baseline (speedup 1.0000x reference)
#include <cuda_runtime.h>
#include <math.h>
#include <stdint.h>

// Problem constants (fixed by the dataset)
#define BATCH   16
#define NQ      2048
#define MK      2048
#define DH      128
#define DV      128

// Tiling
#define BM      64        // query rows per CTA
#define BN      64        // key cols per block
#define NTHREADS 128

// Padded smem strides (floats) — chosen so LDS.128 across 8 lanes hits 32 distinct banks
#define QSTR    132
#define KSTR    132
#define VSTR    132
#define PSTR    68

#define SCALE   0.08838834764831843f   // 1/sqrt(128)

__global__ __launch_bounds__(NTHREADS, 2)
void fa_fp32_kernel(const float* __restrict__ q,
                    const float* __restrict__ k,
                    const float* __restrict__ v,
                    const int*   __restrict__ pad,
                    float*       __restrict__ out)
{
    extern __shared__ float sm[];
    float* sQ  = sm;                       // BM * QSTR
    float* sKP = sm + BM * QSTR;           // BN * KSTR  (K tile; reused as P with stride PSTR)
    float* sV  = sKP + BN * KSTR;          // BN * VSTR

    const int tid  = threadIdx.x;
    const int bIdx = blockIdx.x;
    const int b    = bIdx % BATCH;
    // heavy tiles (large causal range) scheduled first to balance waves
    const int tile = (NQ / BM - 1) - (bIdx / BATCH);

    const int keylen = MK - pad[b];        // keys j >= keylen are zeroed -> score 0.0

    const int g  = tid >> 3;               // row group 0..15
    const int c8 = tid & 7;                // col lane 0..7
    const int r0 = g * 4;                  // this thread owns rows r0..r0+3

    // ---- load Q tile (coalesced float4, swizzle-free padded smem) ----
    const float* qbase = q + ((size_t)b * NQ + (size_t)tile * BM) * DH;
    #pragma unroll
    for (int it = 0; it < (BM * DH / 4) / NTHREADS; ++it) {
        int idx = tid + it * NTHREADS;     // float4 index
        int row = idx >> 5;                // DH/4 = 32 float4 per row
        int c4  = idx & 31;
        float4 val = *(const float4*)(qbase + (size_t)row * DH + c4 * 4);
        *(float4*)(sQ + row * QSTR + c4 * 4) = val;
    }

    // ---- per-row online-softmax state + output accumulator ----
    float m_i[4], l_i[4];
    float o[4][16];
    #pragma unroll
    for (int ii = 0; ii < 4; ++ii) {
        m_i[ii] = -1e30f;
        l_i[ii] = 0.0f;
        #pragma unroll
        for (int c = 0; c < 16; ++c) o[ii][c] = 0.0f;
    }

    const int nkb = tile + 1;              // causal: only key blocks with j <= i_max
    const float* kbase = k + (size_t)b * MK * DH;
    const float* vbase = v + (size_t)b * MK * DV;

    for (int kb = 0; kb < nkb; ++kb) {
        __syncthreads();   // Q visible (iter 0) / previous P,V reads complete

        // ---- load K and V blocks ----
        #pragma unroll
        for (int it = 0; it < (BN * DH / 4) / NTHREADS; ++it) {
            int idx = tid + it * NTHREADS;
            int row = idx >> 5;
            int c4  = idx & 31;
            size_t grow = (size_t)(kb * BN + row);
            *(float4*)(sKP + row * KSTR + c4 * 4) =
                *(const float4*)(kbase + grow * DH + c4 * 4);
            *(float4*)(sV + row * VSTR + c4 * 4) =
                *(const float4*)(vbase + grow * DV + c4 * 4);
        }
        __syncthreads();

        // ---- S = Q * K^T : 4x8 microtile per thread ----
        float acc[4][8];
        #pragma unroll
        for (int ii = 0; ii < 4; ++ii)
            #pragma unroll
            for (int jj = 0; jj < 8; ++jj) acc[ii][jj] = 0.0f;

        #pragma unroll 4
        for (int d4 = 0; d4 < DH / 4; ++d4) {
            float4 qf[4];
            #pragma unroll
            for (int ii = 0; ii < 4; ++ii)
                qf[ii] = *(const float4*)(sQ + (r0 + ii) * QSTR + d4 * 4);
            #pragma unroll
            for (int jj = 0; jj < 8; ++jj) {
                float4 kf = *(const float4*)(sKP + (c8 + 8 * jj) * KSTR + d4 * 4);
                #pragma unroll
                for (int ii = 0; ii < 4; ++ii) {
                    acc[ii][jj] = fmaf(qf[ii].x, kf.x, acc[ii][jj]);
                    acc[ii][jj] = fmaf(qf[ii].y, kf.y, acc[ii][jj]);
                    acc[ii][jj] = fmaf(qf[ii].z, kf.z, acc[ii][jj]);
                    acc[ii][jj] = fmaf(qf[ii].w, kf.w, acc[ii][jj]);
                }
            }
        }

        __syncthreads();   // all K reads done; sKP can be overwritten with P

        // ---- masking + online softmax (registers + shfl within 8-lane row group) ----
        #pragma unroll
        for (int ii = 0; ii < 4; ++ii) {
            const int irow = tile * BM + r0 + ii;
            float rm = -1e30f;
            float s[8];
            #pragma unroll
            for (int jj = 0; jj < 8; ++jj) {
                const int jcol = kb * BN + c8 + 8 * jj;
                float sv = acc[ii][jj] * SCALE;
                if (jcol >= keylen) sv = 0.0f;     // zeroed key -> exact 0 score
                if (jcol > irow)    sv = -1e30f;   // causal mask -> exp underflows to 0
                s[jj] = sv;
                rm = fmaxf(rm, sv);
            }
            rm = fmaxf(rm, __shfl_xor_sync(0xffffffffu, rm, 1));
            rm = fmaxf(rm, __shfl_xor_sync(0xffffffffu, rm, 2));
            rm = fmaxf(rm, __shfl_xor_sync(0xffffffffu, rm, 4));
            const float mnew = fmaxf(m_i[ii], rm);

            float rs = 0.0f;
            #pragma unroll
            for (int jj = 0; jj < 8; ++jj) {
                float e = __expf(s[jj] - mnew);
                s[jj] = e;
                rs += e;
            }
            rs += __shfl_xor_sync(0xffffffffu, rs, 1);
            rs += __shfl_xor_sync(0xffffffffu, rs, 2);
            rs += __shfl_xor_sync(0xffffffffu, rs, 4);

            const float alpha = __expf(m_i[ii] - mnew);
            m_i[ii] = mnew;
            l_i[ii] = l_i[ii] * alpha + rs;
            #pragma unroll
            for (int c = 0; c < 16; ++c) o[ii][c] *= alpha;

            // write P into the (retired) K buffer
            #pragma unroll
            for (int jj = 0; jj < 8; ++jj)
                sKP[(r0 + ii) * PSTR + c8 + 8 * jj] = s[jj];
        }
        __syncthreads();

        // ---- O += P * V : 4x16 microtile per thread ----
        #pragma unroll 4
        for (int j0 = 0; j0 < BN; j0 += 4) {
            float pr[4][4];
            #pragma unroll
            for (int ii = 0; ii < 4; ++ii)
                *reinterpret_cast<float4*>(pr[ii]) =
                    *(const float4*)(sKP + (r0 + ii) * PSTR + j0);
            #pragma unroll
            for (int jj = 0; jj < 4; ++jj) {
                float4 vv[4];
                #pragma unroll
                for (int kk = 0; kk < 4; ++kk)
                    vv[kk] = *(const float4*)(sV + (j0 + jj) * VSTR + c8 * 4 + 32 * kk);
                #pragma unroll
                for (int ii = 0; ii < 4; ++ii) {
                    const float pij = pr[ii][jj];
                    #pragma unroll
                    for (int kk = 0; kk < 4; ++kk) {
                        o[ii][kk * 4 + 0] = fmaf(pij, vv[kk].x, o[ii][kk * 4 + 0]);
                        o[ii][kk * 4 + 1] = fmaf(pij, vv[kk].y, o[ii][kk * 4 + 1]);
                        o[ii][kk * 4 + 2] = fmaf(pij, vv[kk].z, o[ii][kk * 4 + 2]);
                        o[ii][kk * 4 + 3] = fmaf(pij, vv[kk].w, o[ii][kk * 4 + 3]);
                    }
                }
            }
        }
    }

    // ---- epilogue: normalize and store (coalesced float4) ----
    float* obase = out + ((size_t)b * NQ + (size_t)tile * BM) * DV;
    #pragma unroll
    for (int ii = 0; ii < 4; ++ii) {
        const float inv = 1.0f / l_i[ii];
        #pragma unroll
        for (int kk = 0; kk < 4; ++kk) {
            float4 val;
            val.x = o[ii][kk * 4 + 0] * inv;
            val.y = o[ii][kk * 4 + 1] * inv;
            val.z = o[ii][kk * 4 + 2] * inv;
            val.w = o[ii][kk * 4 + 3] * inv;
            *(float4*)(obase + (size_t)(r0 + ii) * DV + c8 * 4 + 32 * kk) = val;
        }
    }
}

extern "C" void kernel_launch(void* const* d_in, const int* in_sizes, int n_in,
                              void* d_out, int out_size)
{
    const float* q   = (const float*)d_in[0];
    const float* k   = (const float*)d_in[1];
    const float* v   = (const float*)d_in[2];
    const int*   pad = (const int*)d_in[3];
    float* out = (float*)d_out;

    const size_t smem = (size_t)(BM * QSTR + BN * KSTR + BN * VSTR) * sizeof(float);
    cudaFuncSetAttribute(fa_fp32_kernel,
                         cudaFuncAttributeMaxDynamicSharedMemorySize, (int)smem);

    dim3 grid((NQ / BM) * BATCH);   // 512 CTAs
    fa_fp32_kernel<<<grid, NTHREADS, smem>>>(q, k, v, pad, out);
}

// round 5
// speedup vs baseline: 2.6991x; 2.6991x over previous
#include <cuda_runtime.h>
#include <cuda_bf16.h>
#include <math.h>
#include <stdint.h>

// Problem constants
#define BATCH   16
#define NQ      2048
#define MK      2048
#define DH      128
#define DV      128

// Tiling
#define BM      64
#define BN      64
#define NTHREADS 128          // 4 warps; warp w owns rows [16w, 16w+16)

#define SCALE   0.08838834764831843f   // 1/sqrt(128)

// smem layout (bf16 elements): 6 buffers of 64x128
#define TILE_ELEMS (64 * 128)
#define OFF_QHI 0
#define OFF_QLO (TILE_ELEMS)
#define OFF_KHI (2 * TILE_ELEMS)
#define OFF_KLO (3 * TILE_ELEMS)
#define OFF_VHI (4 * TILE_ELEMS)
#define OFF_VLO (5 * TILE_ELEMS)
#define SMEM_ELEMS (6 * TILE_ELEMS)   // 49152 bf16 = 96 KB

// XOR swizzle: rows of 128 bf16 (256B); 16B chunk index ^= (row & 7)
__device__ __forceinline__ int swz(int row, int d) {
    return row * 128 + ((((d >> 3) ^ (row & 7)) << 3) | (d & 7));
}

__device__ __forceinline__ uint32_t sptr(const void* p) {
    return (uint32_t)__cvta_generic_to_shared(p);
}

__device__ __forceinline__ void ldsm_x4(uint32_t addr, uint32_t& r0, uint32_t& r1,
                                        uint32_t& r2, uint32_t& r3) {
    asm volatile("ldmatrix.sync.aligned.m8n8.x4.shared.b16 {%0,%1,%2,%3}, [%4];"
                 : "=r"(r0), "=r"(r1), "=r"(r2), "=r"(r3) : "r"(addr));
}

__device__ __forceinline__ void ldsm_x4_t(uint32_t addr, uint32_t& r0, uint32_t& r1,
                                          uint32_t& r2, uint32_t& r3) {
    asm volatile("ldmatrix.sync.aligned.m8n8.x4.trans.shared.b16 {%0,%1,%2,%3}, [%4];"
                 : "=r"(r0), "=r"(r1), "=r"(r2), "=r"(r3) : "r"(addr));
}

__device__ __forceinline__ void mma_bf16(float* c, const uint32_t* a,
                                         uint32_t b0, uint32_t b1) {
    asm volatile(
        "mma.sync.aligned.m16n8k16.row.col.f32.bf16.bf16.f32 "
        "{%0,%1,%2,%3}, {%4,%5,%6,%7}, {%8,%9}, {%0,%1,%2,%3};"
        : "+f"(c[0]), "+f"(c[1]), "+f"(c[2]), "+f"(c[3])
        : "r"(a[0]), "r"(a[1]), "r"(a[2]), "r"(a[3]), "r"(b0), "r"(b1));
}

__device__ __forceinline__ uint32_t pack_bf16(float x, float y) {
    __nv_bfloat162 h = __floats2bfloat162_rn(x, y);
    return *reinterpret_cast<uint32_t*>(&h);
}

// Convert a float4 to hi/lo bf16 and store 8B each into swizzled smem
__device__ __forceinline__ void cvt_store(float4 x, __nv_bfloat16* hi,
                                          __nv_bfloat16* lo, int off) {
    __nv_bfloat16 bx = __float2bfloat16_rn(x.x);
    __nv_bfloat16 by = __float2bfloat16_rn(x.y);
    __nv_bfloat16 bz = __float2bfloat16_rn(x.z);
    __nv_bfloat16 bw = __float2bfloat16_rn(x.w);
    uint2 uh;
    uh.x = pack_bf16(__bfloat162float(bx), __bfloat162float(by));
    uh.y = pack_bf16(__bfloat162float(bz), __bfloat162float(bw));
    // pack_bf16 above re-rounds exact bf16 values -> identical bits; cheaper path:
    {
        __nv_bfloat162 h0 = __halves2bfloat162(bx, by);
        __nv_bfloat162 h1 = __halves2bfloat162(bz, bw);
        uh.x = *reinterpret_cast<uint32_t*>(&h0);
        uh.y = *reinterpret_cast<uint32_t*>(&h1);
    }
    uint2 ul;
    ul.x = pack_bf16(x.x - __bfloat162float(bx), x.y - __bfloat162float(by));
    ul.y = pack_bf16(x.z - __bfloat162float(bz), x.w - __bfloat162float(bw));
    *reinterpret_cast<uint2*>(hi + off) = uh;
    *reinterpret_cast<uint2*>(lo + off) = ul;
}

__global__ __launch_bounds__(NTHREADS, 2)
void fa_hmma_kernel(const float* __restrict__ q,
                    const float* __restrict__ k,
                    const float* __restrict__ v,
                    const int*   __restrict__ pad,
                    float*       __restrict__ out)
{
    extern __shared__ __nv_bfloat16 sm[];
    __nv_bfloat16* sQhi = sm + OFF_QHI;
    __nv_bfloat16* sQlo = sm + OFF_QLO;
    __nv_bfloat16* sKhi = sm + OFF_KHI;
    __nv_bfloat16* sKlo = sm + OFF_KLO;
    __nv_bfloat16* sVhi = sm + OFF_VHI;
    __nv_bfloat16* sVlo = sm + OFF_VLO;

    const int tid  = threadIdx.x;
    const int lane = tid & 31;
    const int warp = tid >> 5;
    const int bIdx = blockIdx.x;
    const int b    = bIdx % BATCH;
    const int tile = (NQ / BM - 1) - (bIdx / BATCH);  // heavy tiles first

    const int keylen = MK - pad[b];

    // ---- stage Q (fp32 -> bf16 hi/lo, swizzled) ----
    const float* qbase = q + ((size_t)b * NQ + (size_t)tile * BM) * DH;
    #pragma unroll
    for (int i = 0; i < 16; ++i) {
        int f   = tid + i * NTHREADS;     // float4 index, 0..2047
        int row = f >> 5;
        int c4  = f & 31;
        int off = row * 128 + ((((c4 >> 1) ^ (row & 7)) << 3) | ((c4 & 1) * 4));
        float4 val = *(const float4*)(qbase + (size_t)row * DH + c4 * 4);
        cvt_store(val, sQhi, sQlo, off);
    }
    __syncthreads();

    // ---- load persistent Q fragments (A operand, m16 x k16 per chunk) ----
    const int r0w = warp * 16;
    uint32_t qhi[8][4], qlo[8][4];
    {
        int qrow = r0w + (lane & 15);
        int dsel = (lane >> 4) << 3;      // 0 or 8
        #pragma unroll
        for (int kc = 0; kc < 8; ++kc) {
            uint32_t ah = sptr(sQhi) + 2 * swz(qrow, kc * 16 + dsel);
            ldsm_x4(ah, qhi[kc][0], qhi[kc][1], qhi[kc][2], qhi[kc][3]);
            uint32_t al = sptr(sQlo) + 2 * swz(qrow, kc * 16 + dsel);
            ldsm_x4(al, qlo[kc][0], qlo[kc][1], qlo[kc][2], qlo[kc][3]);
        }
    }

    // ---- per-thread online softmax state (rows rA = r0w+lane/4, rB = +8) ----
    const int rA = tile * BM + r0w + (lane >> 2);
    const int rB = rA + 8;
    float mA = -1e30f, mB = -1e30f, lA = 0.f, lB = 0.f;
    float oacc[16][4];
    #pragma unroll
    for (int t = 0; t < 16; ++t) {
        oacc[t][0] = 0.f; oacc[t][1] = 0.f; oacc[t][2] = 0.f; oacc[t][3] = 0.f;
    }

    const float* kbase = k + (size_t)b * MK * DH;
    const float* vbase = v + (size_t)b * MK * DV;
    const int nkb = tile + 1;

    for (int kb = 0; kb < nkb; ++kb) {
        __syncthreads();   // previous iteration's K/V reads complete

        // ---- stage K, V blocks ----
        const float* kb_p = kbase + (size_t)kb * BN * DH;
        const float* vb_p = vbase + (size_t)kb * BN * DV;
        #pragma unroll
        for (int i = 0; i < 16; ++i) {
            int f   = tid + i * NTHREADS;
            int row = f >> 5;
            int c4  = f & 31;
            int off = row * 128 + ((((c4 >> 1) ^ (row & 7)) << 3) | ((c4 & 1) * 4));
            float4 kv = *(const float4*)(kb_p + (size_t)row * DH + c4 * 4);
            cvt_store(kv, sKhi, sKlo, off);
            float4 vv = *(const float4*)(vb_p + (size_t)row * DV + c4 * 4);
            cvt_store(vv, sVhi, sVlo, off);
        }
        __syncthreads();

        // ---- S = Q K^T (bf16x3 HMMA) ----
        float sacc[8][4];
        #pragma unroll
        for (int nt = 0; nt < 8; ++nt) {
            sacc[nt][0] = 0.f; sacc[nt][1] = 0.f; sacc[nt][2] = 0.f; sacc[nt][3] = 0.f;
        }

        {
            int key   = (lane & 7);           // within n-tile
            int dbase = (lane >> 3) << 3;     // 0,8,16,24
            #pragma unroll
            for (int nt = 0; nt < 8; ++nt) {
                int krow = nt * 8 + key;
                #pragma unroll
                for (int kc2 = 0; kc2 < 4; ++kc2) {
                    int d = kc2 * 32 + dbase;
                    uint32_t kh0, kh1, kh2, kh3, kl0, kl1, kl2, kl3;
                    ldsm_x4(sptr(sKhi) + 2 * swz(krow, d), kh0, kh1, kh2, kh3);
                    ldsm_x4(sptr(sKlo) + 2 * swz(krow, d), kl0, kl1, kl2, kl3);
                    mma_bf16(sacc[nt], qhi[2 * kc2],     kh0, kh1);
                    mma_bf16(sacc[nt], qhi[2 * kc2 + 1], kh2, kh3);
                    mma_bf16(sacc[nt], qhi[2 * kc2],     kl0, kl1);
                    mma_bf16(sacc[nt], qhi[2 * kc2 + 1], kl2, kl3);
                    mma_bf16(sacc[nt], qlo[2 * kc2],     kh0, kh1);
                    mma_bf16(sacc[nt], qlo[2 * kc2 + 1], kh2, kh3);
                }
            }
        }

        // ---- masking + online softmax in MMA fragment layout ----
        const int kbBase = kb * BN;
        const bool needMask = (kb == tile) || (kbBase + BN > keylen);

        float rmA = -1e30f, rmB = -1e30f;
        if (needMask) {
            #pragma unroll
            for (int nt = 0; nt < 8; ++nt) {
                int colbase = kbBase + nt * 8 + 2 * (lane & 3);
                #pragma unroll
                for (int e = 0; e < 2; ++e) {
                    int col = colbase + e;
                    float sv = sacc[nt][e] * SCALE;
                    if (col >= keylen) sv = 0.0f;
                    if (col > rA)      sv = -1e30f;
                    sacc[nt][e] = sv;
                    rmA = fmaxf(rmA, sv);
                    float sw = sacc[nt][e + 2] * SCALE;
                    if (col >= keylen) sw = 0.0f;
                    if (col > rB)      sw = -1e30f;
                    sacc[nt][e + 2] = sw;
                    rmB = fmaxf(rmB, sw);
                }
            }
        } else {
            #pragma unroll
            for (int nt = 0; nt < 8; ++nt) {
                #pragma unroll
                for (int e = 0; e < 2; ++e) {
                    float sv = sacc[nt][e] * SCALE;
                    sacc[nt][e] = sv;  rmA = fmaxf(rmA, sv);
                    float sw = sacc[nt][e + 2] * SCALE;
                    sacc[nt][e + 2] = sw;  rmB = fmaxf(rmB, sw);
                }
            }
        }
        rmA = fmaxf(rmA, __shfl_xor_sync(0xffffffffu, rmA, 1));
        rmA = fmaxf(rmA, __shfl_xor_sync(0xffffffffu, rmA, 2));
        rmB = fmaxf(rmB, __shfl_xor_sync(0xffffffffu, rmB, 1));
        rmB = fmaxf(rmB, __shfl_xor_sync(0xffffffffu, rmB, 2));

        const float mnA = fmaxf(mA, rmA);
        const float mnB = fmaxf(mB, rmB);
        const float alA = __expf(mA - mnA);
        const float alB = __expf(mB - mnB);
        mA = mnA;  mB = mnB;

        float sumA = 0.f, sumB = 0.f;
        #pragma unroll
        for (int nt = 0; nt < 8; ++nt) {
            #pragma unroll
            for (int e = 0; e < 2; ++e) {
                float p0 = __expf(sacc[nt][e] - mnA);
                sacc[nt][e] = p0;  sumA += p0;
                float p1 = __expf(sacc[nt][e + 2] - mnB);
                sacc[nt][e + 2] = p1;  sumB += p1;
            }
        }
        lA = lA * alA + sumA;
        lB = lB * alB + sumB;

        #pragma unroll
        for (int t = 0; t < 16; ++t) {
            oacc[t][0] *= alA;  oacc[t][1] *= alA;
            oacc[t][2] *= alB;  oacc[t][3] *= alB;
        }

        // ---- O += P V (P frags from S accumulators, bf16x3) ----
        {
            int vkey = (lane & 15);
            int nsel = (lane >> 4) << 3;   // 0 or 8
            #pragma unroll
            for (int kt = 0; kt < 4; ++kt) {
                uint32_t ahi[4], alo[4];
                {
                    const float* p0 = sacc[2 * kt];
                    const float* p1 = sacc[2 * kt + 1];
                    __nv_bfloat162 h;
                    h = __floats2bfloat162_rn(p0[0], p0[1]);
                    ahi[0] = *reinterpret_cast<uint32_t*>(&h);
                    alo[0] = pack_bf16(p0[0] - __bfloat162float(h.x),
                                       p0[1] - __bfloat162float(h.y));
                    h = __floats2bfloat162_rn(p0[2], p0[3]);
                    ahi[1] = *reinterpret_cast<uint32_t*>(&h);
                    alo[1] = pack_bf16(p0[2] - __bfloat162float(h.x),
                                       p0[3] - __bfloat162float(h.y));
                    h = __floats2bfloat162_rn(p1[0], p1[1]);
                    ahi[2] = *reinterpret_cast<uint32_t*>(&h);
                    alo[2] = pack_bf16(p1[0] - __bfloat162float(h.x),
                                       p1[1] - __bfloat162float(h.y));
                    h = __floats2bfloat162_rn(p1[2], p1[3]);
                    ahi[3] = *reinterpret_cast<uint32_t*>(&h);
                    alo[3] = pack_bf16(p1[2] - __bfloat162float(h.x),
                                       p1[3] - __bfloat162float(h.y));
                }
                int krow = kt * 16 + vkey;
                #pragma unroll
                for (int nt2 = 0; nt2 < 8; ++nt2) {
                    int n0 = nt2 * 16 + nsel;
                    uint32_t vh0, vh1, vh2, vh3, vl0, vl1, vl2, vl3;
                    ldsm_x4_t(sptr(sVhi) + 2 * swz(krow, n0), vh0, vh1, vh2, vh3);
                    ldsm_x4_t(sptr(sVlo) + 2 * swz(krow, n0), vl0, vl1, vl2, vl3);
                    mma_bf16(oacc[2 * nt2],     ahi, vh0, vh1);
                    mma_bf16(oacc[2 * nt2 + 1], ahi, vh2, vh3);
                    mma_bf16(oacc[2 * nt2],     ahi, vl0, vl1);
                    mma_bf16(oacc[2 * nt2 + 1], ahi, vl2, vl3);
                    mma_bf16(oacc[2 * nt2],     alo, vh0, vh1);
                    mma_bf16(oacc[2 * nt2 + 1], alo, vh2, vh3);
                }
            }
        }
    }

    // ---- epilogue: reduce l across the 4-lane row group, normalize, store ----
    lA += __shfl_xor_sync(0xffffffffu, lA, 1);
    lA += __shfl_xor_sync(0xffffffffu, lA, 2);
    lB += __shfl_xor_sync(0xffffffffu, lB, 1);
    lB += __shfl_xor_sync(0xffffffffu, lB, 2);
    const float invA = 1.0f / lA;
    const float invB = 1.0f / lB;

    float* obase = out + (size_t)b * NQ * DV;
    #pragma unroll
    for (int t = 0; t < 16; ++t) {
        int col = t * 8 + 2 * (lane & 3);
        float2 va = make_float2(oacc[t][0] * invA, oacc[t][1] * invA);
        float2 vb = make_float2(oacc[t][2] * invB, oacc[t][3] * invB);
        *(float2*)(obase + (size_t)rA * DV + col) = va;
        *(float2*)(obase + (size_t)rB * DV + col) = vb;
    }
}

extern "C" void kernel_launch(void* const* d_in, const int* in_sizes, int n_in,
                              void* d_out, int out_size)
{
    const float* q   = (const float*)d_in[0];
    const float* k   = (const float*)d_in[1];
    const float* v   = (const float*)d_in[2];
    const int*   pad = (const int*)d_in[3];
    float* out = (float*)d_out;

    const size_t smem = (size_t)SMEM_ELEMS * sizeof(__nv_bfloat16);  // 96 KB
    cudaFuncSetAttribute(fa_hmma_kernel,
                         cudaFuncAttributeMaxDynamicSharedMemorySize, (int)smem);

    dim3 grid((NQ / BM) * BATCH);   // 512 CTAs
    fa_hmma_kernel<<<grid, NTHREADS, smem>>>(q, k, v, pad, out);
}